// round 1
// baseline (speedup 1.0000x reference)
#include <cuda_runtime.h>
#include <math.h>

#define BB   2
#define SS   512
#define DM   768
#define HH   12
#define DH   64
#define EA   4
#define EF   8
#define DFF  3072
#define NTOK (BB*SS)
#define CAP  160
#define NE   (NTOK*2)

__device__ float g_xln1[NTOK*DM];
__device__ float g_q[NTOK*DM];
__device__ float g_k[NTOK*DM];
__device__ float g_r[NTOK*HH*EA];
__device__ int   g_idx[NTOK*HH];
__device__ int   g_hard[HH*EA];
__device__ float g_vproj[HH*NTOK*DH];
__device__ float g_p[HH*BB*SS*SS];
__device__ float g_ao[HH*NTOK*DH];
__device__ float g_x1[NTOK*DM];
__device__ float g_xln2[NTOK*DM];
__device__ float g_gl[NTOK*EF];
__device__ int   g_ee[NE];
__device__ int   g_epos[NE];
__device__ float g_ew[NE];
__device__ int   g_ekeep[NE];
__device__ float g_buf[EF*CAP*DM];
__device__ float g_hmid[EF*CAP*DFF];
__device__ float g_ybuf[EF*CAP*DM];
__device__ float g_aux[2];

__global__ __launch_bounds__(256) void ln_kernel(const float* __restrict__ x,
                                                 const float* __restrict__ g,
                                                 const float* __restrict__ b,
                                                 float* __restrict__ out)
{
    int n = blockIdx.x;
    const float* row = x + (size_t)n * DM;
    float s = 0.f, ss = 0.f;
    for (int d = threadIdx.x; d < DM; d += 256) {
        float v = row[d];
        s += v; ss += v * v;
    }
    __shared__ float shs[8], shq[8];
    int lane = threadIdx.x & 31, wid = threadIdx.x >> 5;
    #pragma unroll
    for (int o = 16; o; o >>= 1) { s += __shfl_xor_sync(~0u, s, o); ss += __shfl_xor_sync(~0u, ss, o); }
    if (lane == 0) { shs[wid] = s; shq[wid] = ss; }
    __syncthreads();
    if (threadIdx.x == 0) {
        float ts = 0, tq = 0;
        for (int i = 0; i < 8; i++) { ts += shs[i]; tq += shq[i]; }
        shs[0] = ts; shq[0] = tq;
    }
    __syncthreads();
    float mu = shs[0] / DM;
    float var = shq[0] / DM - mu * mu;
    float inv = rsqrtf(var + 1e-5f);
    for (int d = threadIdx.x; d < DM; d += 256)
        out[(size_t)n * DM + d] = (row[d] - mu) * inv * g[d] + b[d];
}

template<int TRANSA, int RELU>
__global__ __launch_bounds__(256) void gemm_kernel(const float* __restrict__ A,
                                                   const float* __restrict__ Bm,
                                                   float* __restrict__ C,
                                                   int M, int N, int K,
                                                   size_t sA, size_t sB, size_t sC)
{
    int z = blockIdx.z;
    A  += (size_t)z * sA;
    Bm += (size_t)z * sB;
    C  += (size_t)z * sC;
    int m0 = blockIdx.y * 64, n0 = blockIdx.x * 64;
    int tid = threadIdx.x;
    int tx = tid & 15, ty = tid >> 4;

    __shared__ float As[16][64];
    __shared__ float Bs[16][64];
    float acc[4][4] = {};

    for (int k0 = 0; k0 < K; k0 += 16) {
        if (TRANSA == 0) {
            int kl = tid & 15, mb = (tid >> 4) * 4;
            #pragma unroll
            for (int i = 0; i < 4; i++) {
                int m = m0 + mb + i;
                As[kl][mb + i] = (m < M) ? A[(size_t)m * K + k0 + kl] : 0.f;
            }
        } else {
            int ml = tid & 63, kb = (tid >> 6) * 4;
            int m = m0 + ml;
            #pragma unroll
            for (int i = 0; i < 4; i++)
                As[kb + i][ml] = (m < M) ? A[(size_t)(k0 + kb + i) * M + m] : 0.f;
        }
        {
            int nl = tid & 63, kb = (tid >> 6) * 4;
            int n = n0 + nl;
            #pragma unroll
            for (int i = 0; i < 4; i++)
                Bs[kb + i][nl] = (n < N) ? Bm[(size_t)(k0 + kb + i) * N + n] : 0.f;
        }
        __syncthreads();
        #pragma unroll
        for (int k = 0; k < 16; k++) {
            float4 a  = *(const float4*)&As[k][ty * 4];
            float4 bv = *(const float4*)&Bs[k][tx * 4];
            float av[4] = {a.x, a.y, a.z, a.w};
            float bw[4] = {bv.x, bv.y, bv.z, bv.w};
            #pragma unroll
            for (int i = 0; i < 4; i++)
                #pragma unroll
                for (int j = 0; j < 4; j++)
                    acc[i][j] += av[i] * bw[j];
        }
        __syncthreads();
    }
    #pragma unroll
    for (int i = 0; i < 4; i++) {
        int m = m0 + ty * 4 + i;
        if (m >= M) continue;
        #pragma unroll
        for (int j = 0; j < 4; j++) {
            int n = n0 + tx * 4 + j;
            if (n >= N) continue;
            float v = acc[i][j];
            if (RELU) v = fmaxf(v, 0.f);
            C[(size_t)m * N + n] = v;
        }
    }
}

__global__ void init_hard_kernel()
{
    if (threadIdx.x < HH * EA) g_hard[threadIdx.x] = 0;
}

__global__ void argmax_kernel()
{
    int i = blockIdx.x * blockDim.x + threadIdx.x;
    if (i >= NTOK * HH) return;
    int n = i / HH, h = i % HH;
    const float* g = g_r + (size_t)n * (HH * EA) + h * EA;
    int best = 0; float bv = g[0];
    #pragma unroll
    for (int a = 1; a < EA; a++) if (g[a] > bv) { bv = g[a]; best = a; }
    g_idx[i] = best;
    atomicAdd(&g_hard[h * EA + best], 1);
}

__global__ void aux1_kernel()
{
    if (threadIdx.x != 0) return;
    float e[HH * EA];
    float tot = 0.f;
    for (int i = 0; i < HH * EA; i++) { e[i] = 0.01f * (float)g_hard[i] / (float)NTOK; tot += e[i]; }
    float a = 0.f;
    for (int i = 0; i < HH * EA; i++) { float pr = e[i] / (tot + 1e-9f); a += pr * pr; }
    g_aux[0] = a * (float)(EA * HH);
}

__global__ __launch_bounds__(64) void vproj_kernel(const float* __restrict__ Wv)
{
    int n = blockIdx.x, h = blockIdx.y, e = threadIdx.x;
    __shared__ float xs[DH];
    xs[e] = g_xln1[(size_t)n * DM + h * DH + e];
    __syncthreads();
    int a = g_idx[n * HH + h];
    const float* W = Wv + ((size_t)(h * EA + a)) * DH * DH;
    float acc = 0.f;
    #pragma unroll
    for (int d = 0; d < DH; d++) acc += xs[d] * W[d * DH + e];
    g_vproj[((size_t)h * NTOK + n) * DH + e] = acc;
}

__global__ __launch_bounds__(64) void oproj_kernel(const float* __restrict__ Wo,
                                                   const float* __restrict__ xres)
{
    int n = blockIdx.x, h = blockIdx.y, e = threadIdx.x;
    __shared__ float xs[DH];
    xs[e] = g_ao[((size_t)h * NTOK + n) * DH + e];
    __syncthreads();
    int a = g_idx[n * HH + h];
    const float* W = Wo + ((size_t)(h * EA + a)) * DH * DH;
    float acc = 0.f;
    #pragma unroll
    for (int d = 0; d < DH; d++) acc += xs[d] * W[d * DH + e];
    size_t off = (size_t)n * DM + h * DH + e;
    g_x1[off] = xres[off] + acc;
}

__global__ __launch_bounds__(256) void scores_kernel(const float* __restrict__ mask)
{
    int bh = blockIdx.x;
    int h = bh >> 1, b = bh & 1;
    int s0 = blockIdx.y * 16;
    int tid = threadIdx.x;
    int sIdx = tid >> 4, tIdx = tid & 15;

    __shared__ float qs[16][64];
    __shared__ float ks[64][65];

    for (int i = tid; i < 16 * 64; i += 256) {
        int s = i >> 6, d = i & 63;
        qs[s][d] = g_q[(size_t)(b * SS + s0 + s) * DM + h * DH + d];
    }

    float sc[32];
    int sg = s0 + sIdx;
    for (int c = 0; c < 8; c++) {
        int t0 = c * 64;
        __syncthreads();
        for (int i = tid; i < 64 * 64; i += 256) {
            int t = i >> 6, d = i & 63;
            ks[t][d] = g_k[(size_t)(b * SS + t0 + t) * DM + h * DH + d];
        }
        __syncthreads();
        #pragma unroll
        for (int j = 0; j < 4; j++) {
            int tl = tIdx * 4 + j;
            float a = 0.f;
            #pragma unroll
            for (int d = 0; d < DH; d++) a += qs[sIdx][d] * ks[tl][d];
            sc[c * 4 + j] = a * 0.125f + mask[(size_t)sg * SS + t0 + tl];
        }
    }
    float mx = -1e30f;
    #pragma unroll
    for (int i = 0; i < 32; i++) mx = fmaxf(mx, sc[i]);
    #pragma unroll
    for (int o = 8; o >= 1; o >>= 1) mx = fmaxf(mx, __shfl_xor_sync(0xffffffffu, mx, o, 16));
    float sm = 0.f;
    #pragma unroll
    for (int i = 0; i < 32; i++) { sc[i] = expf(sc[i] - mx); sm += sc[i]; }
    #pragma unroll
    for (int o = 8; o >= 1; o >>= 1) sm += __shfl_xor_sync(0xffffffffu, sm, o, 16);
    float inv = 1.f / sm;
    float* prow = g_p + ((size_t)bh * SS + sg) * SS;
    #pragma unroll
    for (int c = 0; c < 8; c++)
        #pragma unroll
        for (int j = 0; j < 4; j++)
            prow[c * 64 + tIdx * 4 + j] = sc[c * 4 + j] * inv;
}

__global__ __launch_bounds__(256) void route_kernel()
{
    int tid = threadIdx.x;
    __shared__ int   s_e[NE];
    __shared__ float s_p[NE];
    __shared__ int   s_pos[NE];
    __shared__ int   s_keep[NE];
    __shared__ float s_imp[EF];
    __shared__ int   s_cnt[EF];

    for (int n = tid; n < NTOK; n += 256) {
        const float* g = g_gl + (size_t)n * EF;
        int i0 = 0; float v0 = g[0];
        #pragma unroll
        for (int j = 1; j < EF; j++) if (g[j] > v0) { v0 = g[j]; i0 = j; }
        int i1 = -1; float v1 = -1e30f;
        #pragma unroll
        for (int j = 0; j < EF; j++) { if (j == i0) continue; if (g[j] > v1) { v1 = g[j]; i1 = j; } }
        float e1 = expf(v1 - v0);
        float den = 1.f + e1;
        s_e[2 * n] = i0; s_e[2 * n + 1] = i1;
        s_p[2 * n] = 1.f / den; s_p[2 * n + 1] = e1 / den;
    }
    __syncthreads();
    if (tid == 0) {
        int cnt[EF] = {};
        for (int j = 0; j < NE; j++) {
            int e = s_e[j];
            int p = cnt[e]++;
            s_pos[j] = p;
            s_keep[j] = (p < CAP) ? 1 : 0;
        }
    }
    __syncthreads();
    if (tid < EF) { s_imp[tid] = 0.f; s_cnt[tid] = 0; }
    __syncthreads();
    for (int n = tid; n < NTOK; n += 256) {
        float p0 = s_p[2 * n]     * (float)s_keep[2 * n];
        float p1 = s_p[2 * n + 1] * (float)s_keep[2 * n + 1];
        float den = p0 + p1 + 1e-9f;
        float w0 = p0 / den, w1 = p1 / den;
        g_ew[2 * n] = w0;      g_ew[2 * n + 1] = w1;
        g_ee[2 * n] = s_e[2 * n];       g_ee[2 * n + 1] = s_e[2 * n + 1];
        g_epos[2 * n] = s_pos[2 * n];   g_epos[2 * n + 1] = s_pos[2 * n + 1];
        g_ekeep[2 * n] = s_keep[2 * n]; g_ekeep[2 * n + 1] = s_keep[2 * n + 1];
        if (s_keep[2 * n])     { atomicAdd(&s_cnt[s_e[2 * n]], 1);     atomicAdd(&s_imp[s_e[2 * n]], w0); }
        if (s_keep[2 * n + 1]) { atomicAdd(&s_cnt[s_e[2 * n + 1]], 1); atomicAdd(&s_imp[s_e[2 * n + 1]], w1); }
    }
    __syncthreads();
    if (tid == 0) {
        float ct = 0.f, it = 0.f;
        for (int e = 0; e < EF; e++) { ct += (float)s_cnt[e]; it += s_imp[e]; }
        float a = 0.f;
        for (int e = 0; e < EF; e++)
            a += ((float)s_cnt[e] / (ct + 1e-9f)) * (s_imp[e] / (it + 1e-9f));
        g_aux[1] = a * (float)EF;
    }
}

__global__ __launch_bounds__(192) void scatter_kernel()
{
    int j = blockIdx.x;
    if (!g_ekeep[j]) return;
    int tok = j >> 1;
    float4* dst = (float4*)(g_buf + ((size_t)g_ee[j] * CAP + g_epos[j]) * DM);
    const float4* src = (const float4*)(g_xln2 + (size_t)tok * DM);
    for (int d = threadIdx.x; d < DM / 4; d += 192) dst[d] = src[d];
}

__global__ __launch_bounds__(256) void output_kernel(float* __restrict__ out, int out_size)
{
    int n = blockIdx.x, tid = threadIdx.x;
    float w0 = g_ew[2 * n], w1 = g_ew[2 * n + 1];
    const float* y0 = g_ybuf + ((size_t)g_ee[2 * n]     * CAP + g_epos[2 * n])     * DM;
    const float* y1 = g_ybuf + ((size_t)g_ee[2 * n + 1] * CAP + g_epos[2 * n + 1]) * DM;
    bool k0 = g_ekeep[2 * n] != 0, k1 = g_ekeep[2 * n + 1] != 0;
    for (int d = tid; d < DM; d += 256) {
        float f = 0.f;
        if (k0) f += w0 * y0[d];
        if (k1) f += w1 * y1[d];
        out[(size_t)n * DM + d] = g_x1[(size_t)n * DM + d] + f;
    }
    if (n == 0 && tid == 0 && out_size > NTOK * DM)
        out[NTOK * DM] = g_aux[0] + g_aux[1];
}

extern "C" void kernel_launch(void* const* d_in, const int* in_sizes, int n_in,
                              void* d_out, int out_size)
{
    const float* x        = (const float*)d_in[0];
    const float* mask     = (const float*)d_in[1];
    const float* ln1_g    = (const float*)d_in[2];
    const float* ln1_b    = (const float*)d_in[3];
    const float* ln2_g    = (const float*)d_in[4];
    const float* ln2_b    = (const float*)d_in[5];
    const float* W_q      = (const float*)d_in[6];
    const float* W_k      = (const float*)d_in[7];
    const float* W_v      = (const float*)d_in[8];
    const float* W_o      = (const float*)d_in[9];
    const float* router_w = (const float*)d_in[10];
    const float* gate_w   = (const float*)d_in[11];
    const float* W1       = (const float*)d_in[12];
    const float* W2       = (const float*)d_in[13];
    float* out = (float*)d_out;

    float *p_xln1, *p_q, *p_k, *p_r, *p_p, *p_vproj, *p_ao, *p_x1, *p_xln2,
          *p_gl, *p_buf, *p_hmid, *p_ybuf;
    cudaGetSymbolAddress((void**)&p_xln1,  g_xln1);
    cudaGetSymbolAddress((void**)&p_q,     g_q);
    cudaGetSymbolAddress((void**)&p_k,     g_k);
    cudaGetSymbolAddress((void**)&p_r,     g_r);
    cudaGetSymbolAddress((void**)&p_p,     g_p);
    cudaGetSymbolAddress((void**)&p_vproj, g_vproj);
    cudaGetSymbolAddress((void**)&p_ao,    g_ao);
    cudaGetSymbolAddress((void**)&p_x1,    g_x1);
    cudaGetSymbolAddress((void**)&p_xln2,  g_xln2);
    cudaGetSymbolAddress((void**)&p_gl,    g_gl);
    cudaGetSymbolAddress((void**)&p_buf,   g_buf);
    cudaGetSymbolAddress((void**)&p_hmid,  g_hmid);
    cudaGetSymbolAddress((void**)&p_ybuf,  g_ybuf);

    init_hard_kernel<<<1, 64>>>();
    ln_kernel<<<NTOK, 256>>>(x, ln1_g, ln1_b, p_xln1);

    gemm_kernel<0,0><<<dim3(DM/64, NTOK/64, 1), 256>>>(p_xln1, W_q, p_q, NTOK, DM, DM, 0, 0, 0);
    gemm_kernel<0,0><<<dim3(DM/64, NTOK/64, 1), 256>>>(p_xln1, W_k, p_k, NTOK, DM, DM, 0, 0, 0);
    gemm_kernel<0,0><<<dim3(1, NTOK/64, 1), 256>>>(p_xln1, router_w, p_r, NTOK, HH*EA, DM, 0, 0, 0);

    argmax_kernel<<<(NTOK*HH + 255)/256, 256>>>();
    aux1_kernel<<<1, 32>>>();

    vproj_kernel<<<dim3(NTOK, HH), 64>>>(W_v);
    scores_kernel<<<dim3(HH*BB, SS/16), 256>>>(mask);

    gemm_kernel<1,0><<<dim3(1, SS/64, HH*BB), 256>>>(p_p, p_vproj, p_ao,
                                                     SS, DH, SS,
                                                     (size_t)SS*SS, (size_t)SS*DH, (size_t)SS*DH);

    oproj_kernel<<<dim3(NTOK, HH), 64>>>(W_o, x);

    ln_kernel<<<NTOK, 256>>>(p_x1, ln2_g, ln2_b, p_xln2);
    gemm_kernel<0,0><<<dim3(1, NTOK/64, 1), 256>>>(p_xln2, gate_w, p_gl, NTOK, EF, DM, 0, 0, 0);

    route_kernel<<<1, 256>>>();
    scatter_kernel<<<NE, 192>>>();

    gemm_kernel<0,1><<<dim3(DFF/64, (CAP+63)/64, EF), 256>>>(p_buf, W1, p_hmid,
                                                             CAP, DFF, DM,
                                                             (size_t)CAP*DM, (size_t)DM*DFF, (size_t)CAP*DFF);
    gemm_kernel<0,0><<<dim3(DM/64, (CAP+63)/64, EF), 256>>>(p_hmid, W2, p_ybuf,
                                                            CAP, DM, DFF,
                                                            (size_t)CAP*DFF, (size_t)DFF*DM, (size_t)CAP*DM);

    output_kernel<<<NTOK, 256>>>(out, out_size);
}